// round 3
// baseline (speedup 1.0000x reference)
#include <cuda_runtime.h>
#include <cuda_bf16.h>
#include <cstdint>

// ---------------------------------------------------------------------------
// vGINMolEncoder: 5-layer GINEConv + virtual node, eval-mode BN, mean-pool.
// All math in fp32. Scratch in __device__ globals (no allocations).
// ---------------------------------------------------------------------------

#define MAXN 200000
#define MAXE 800000
#define MAXG 8000
#define DIM  300
#define HID  600
#define NLAYER 5
#define EPS_BN 1e-5f
#define C4 75            // DIM / 4  (float4 chunks per row)

__device__ float g_h     [(size_t)MAXN * DIM];   // conv input (h or post+vfeat[batch])
__device__ float g_aggr  [(size_t)MAXN * DIM];   // edge aggregation
__device__ float g_hid   [(size_t)MAXN * HID];   // inner MLP hidden
__device__ float g_post  [(size_t)MAXN * DIM];   // conv output
__device__ float g_vfeat [(size_t)MAXG * DIM];
__device__ float g_pooled[(size_t)MAXG * DIM];
__device__ float g_vhid  [(size_t)MAXG * HID];
__device__ float g_cnt   [MAXG];

// ---------------------------------------------------------------------------
// Atom encoder: h[n,:] = sum_{f=0..8} atom_emb[f, x[n,f], :]
// ---------------------------------------------------------------------------
__global__ void atom_encode_kernel(const int* __restrict__ x,
                                   const float* __restrict__ atom_emb,
                                   float* __restrict__ h, int N) {
    int idx = blockIdx.x * blockDim.x + threadIdx.x;
    if (idx >= N * C4) return;
    int n = idx / C4;
    int c = (idx - n * C4) * 4;
    float4 s = make_float4(0.f, 0.f, 0.f, 0.f);
#pragma unroll
    for (int f = 0; f < 9; f++) {
        int v = x[n * 9 + f];
        const float4 e = *(const float4*)(atom_emb + ((size_t)(f * 64 + v)) * DIM + c);
        s.x += e.x; s.y += e.y; s.z += e.z; s.w += e.w;
    }
    *(float4*)(h + (size_t)n * DIM + c) = s;
}

// ---------------------------------------------------------------------------
// Edge message + scatter: aggr[dst] += relu(h[src] + bond_emb_sum(edge_attr))
// ---------------------------------------------------------------------------
__global__ void edge_msg_kernel(const float* __restrict__ h,
                                const int* __restrict__ src,
                                const int* __restrict__ dst,
                                const int* __restrict__ ea,
                                const float* __restrict__ bond_l,   // [3,16,DIM]
                                float* __restrict__ aggr, int E) {
    int idx = blockIdx.x * blockDim.x + threadIdx.x;
    if (idx >= E * C4) return;
    int e  = idx / C4;
    int c  = (idx - e * C4) * 4;
    int s  = src[e];
    int dn = dst[e];
    int a0 = ea[e * 3 + 0], a1 = ea[e * 3 + 1], a2 = ea[e * 3 + 2];
    const float4 b0 = *(const float4*)(bond_l + ((size_t)(0 * 16 + a0)) * DIM + c);
    const float4 b1 = *(const float4*)(bond_l + ((size_t)(1 * 16 + a1)) * DIM + c);
    const float4 b2 = *(const float4*)(bond_l + ((size_t)(2 * 16 + a2)) * DIM + c);
    const float4 hv = *(const float4*)(h + (size_t)s * DIM + c);
    float4 m;
    m.x = fmaxf(hv.x + b0.x + b1.x + b2.x, 0.f);
    m.y = fmaxf(hv.y + b0.y + b1.y + b2.y, 0.f);
    m.z = fmaxf(hv.z + b0.z + b1.z + b2.z, 0.f);
    m.w = fmaxf(hv.w + b0.w + b1.w + b2.w, 0.f);
    float* p = aggr + (size_t)dn * DIM + c;
    atomicAdd(p + 0, m.x);
    atomicAdd(p + 1, m.y);
    atomicAdd(p + 2, m.z);
    atomicAdd(p + 3, m.w);
}

// ---------------------------------------------------------------------------
// h = post + vfeat[batch]
// ---------------------------------------------------------------------------
__global__ void add_vfeat_kernel(const float* __restrict__ post,
                                 const float* __restrict__ vfeat,
                                 const int* __restrict__ batch,
                                 float* __restrict__ h, int N) {
    int idx = blockIdx.x * blockDim.x + threadIdx.x;
    if (idx >= N * C4) return;
    int n = idx / C4;
    int c = (idx - n * C4) * 4;
    int g = batch[n];
    const float4 p = *(const float4*)(post  + (size_t)n * DIM + c);
    const float4 v = *(const float4*)(vfeat + (size_t)g * DIM + c);
    float4 o = make_float4(p.x + v.x, p.y + v.y, p.z + v.z, p.w + v.w);
    *(float4*)(h + (size_t)n * DIM + c) = o;
}

// ---------------------------------------------------------------------------
// pooled[batch[n]] += post[n]
// ---------------------------------------------------------------------------
__global__ void pool_kernel(const float* __restrict__ post,
                            const int* __restrict__ batch,
                            float* __restrict__ pooled, int N) {
    int idx = blockIdx.x * blockDim.x + threadIdx.x;
    if (idx >= N * C4) return;
    int n = idx / C4;
    int c = (idx - n * C4) * 4;
    int g = batch[n];
    const float4 p = *(const float4*)(post + (size_t)n * DIM + c);
    float* q = pooled + (size_t)g * DIM + c;
    atomicAdd(q + 0, p.x);
    atomicAdd(q + 1, p.y);
    atomicAdd(q + 2, p.z);
    atomicAdd(q + 3, p.w);
}

__global__ void count_kernel(const int* __restrict__ batch, float* __restrict__ cnt, int N) {
    int i = blockIdx.x * blockDim.x + threadIdx.x;
    if (i < N) atomicAdd(&cnt[batch[i]], 1.0f);
}

__global__ void vfeat_init_kernel(const float* __restrict__ vn, float* __restrict__ vfeat, int G) {
    int idx = blockIdx.x * blockDim.x + threadIdx.x;
    if (idx >= G * DIM) return;
    vfeat[idx] = vn[idx % DIM];
}

__global__ void out_kernel(const float* __restrict__ pooled, const float* __restrict__ cnt,
                           float* __restrict__ out, int G) {
    int idx = blockIdx.x * blockDim.x + threadIdx.x;
    if (idx >= G * DIM) return;
    int g = idx / DIM;
    out[idx] = pooled[idx] / fmaxf(cnt[g], 1.0f);
}

// ---------------------------------------------------------------------------
// Fused GEMM: C = epilogue((A (+A2)) @ B + bias), epilogue = BN (+ReLU).
// A: [M,K] row-major, B: [K,Nc] row-major, bnp: [4,Nc] (gamma,beta,mean,var).
// Classic 128x128x8 tile, 256 threads, 8x8 micro-tile.
// ---------------------------------------------------------------------------
#define BM 128
#define BN 128
#define BK 8

__global__ __launch_bounds__(256) void gemm_bn_kernel(
    const float* __restrict__ A, const float* __restrict__ A2,
    const float* __restrict__ B, const float* __restrict__ bias,
    const float* __restrict__ bnp, float* __restrict__ C,
    int M, int K, int Nc, int do_relu) {

    __shared__ float As[BK][BM];
    __shared__ float Bs[BK][BN];

    const int tid = threadIdx.x;
    const int tx = tid & 15;          // 0..15  -> 8 output cols each
    const int ty = tid >> 4;          // 0..15  -> 8 output rows each
    const int m0 = blockIdx.y * BM;
    const int n0 = blockIdx.x * BN;

    // global load mapping
    const int a_row = tid >> 1;               // 0..127
    const int a_col = (tid & 1) * 4;          // 0 or 4
    const int b_row = tid >> 5;               // 0..7
    const int b_col = (tid & 31) * 4;         // 0..124

    float acc[8][8];
#pragma unroll
    for (int i = 0; i < 8; i++)
#pragma unroll
        for (int j = 0; j < 8; j++) acc[i][j] = 0.f;

    for (int k0 = 0; k0 < K; k0 += BK) {
        // --- load A tile (transposed into As[k][m]) ---
        {
            int gr = m0 + a_row;
            int gc = k0 + a_col;
            float4 av = make_float4(0.f, 0.f, 0.f, 0.f);
            if (gr < M && gc < K) {           // K % 4 == 0 always
                av = *(const float4*)(A + (size_t)gr * K + gc);
                if (A2) {
                    const float4 a2 = *(const float4*)(A2 + (size_t)gr * K + gc);
                    av.x += a2.x; av.y += a2.y; av.z += a2.z; av.w += a2.w;
                }
            }
            As[a_col + 0][a_row] = av.x;
            As[a_col + 1][a_row] = av.y;
            As[a_col + 2][a_row] = av.z;
            As[a_col + 3][a_row] = av.w;
        }
        // --- load B tile ---
        {
            int gr = k0 + b_row;
            int gc = n0 + b_col;
            float4 bv = make_float4(0.f, 0.f, 0.f, 0.f);
            if (gr < K && gc < Nc)            // Nc % 4 == 0 always
                bv = *(const float4*)(B + (size_t)gr * Nc + gc);
            *(float4*)&Bs[b_row][b_col] = bv;
        }
        __syncthreads();

#pragma unroll
        for (int kk = 0; kk < BK; kk++) {
            float a[8], b[8];
            *(float4*)&a[0] = *(float4*)&As[kk][ty * 8];
            *(float4*)&a[4] = *(float4*)&As[kk][ty * 8 + 4];
            *(float4*)&b[0] = *(float4*)&Bs[kk][tx * 8];
            *(float4*)&b[4] = *(float4*)&Bs[kk][tx * 8 + 4];
#pragma unroll
            for (int i = 0; i < 8; i++)
#pragma unroll
                for (int j = 0; j < 8; j++)
                    acc[i][j] += a[i] * b[j];
        }
        __syncthreads();
    }

    // --- epilogue: bias -> BN -> (ReLU) ---
    float sc[8], sh[8], bb[8];
#pragma unroll
    for (int j = 0; j < 8; j++) {
        int col = n0 + tx * 8 + j;
        if (col < Nc) {
            bb[j] = bias[col];
            float ga = bnp[col];
            float be = bnp[Nc + col];
            float mu = bnp[2 * Nc + col];
            float va = bnp[3 * Nc + col];
            float s = ga * rsqrtf(va + EPS_BN);
            sc[j] = s;
            sh[j] = be - mu * s;
        } else { sc[j] = 0.f; sh[j] = 0.f; bb[j] = 0.f; }
    }

#pragma unroll
    for (int i = 0; i < 8; i++) {
        int row = m0 + ty * 8 + i;
        if (row >= M) continue;
#pragma unroll
        for (int jj = 0; jj < 2; jj++) {
            int col = n0 + tx * 8 + jj * 4;
            if (col >= Nc) continue;
            float4 o;
            float v0 = (acc[i][jj * 4 + 0] + bb[jj * 4 + 0]) * sc[jj * 4 + 0] + sh[jj * 4 + 0];
            float v1 = (acc[i][jj * 4 + 1] + bb[jj * 4 + 1]) * sc[jj * 4 + 1] + sh[jj * 4 + 1];
            float v2 = (acc[i][jj * 4 + 2] + bb[jj * 4 + 2]) * sc[jj * 4 + 2] + sh[jj * 4 + 2];
            float v3 = (acc[i][jj * 4 + 3] + bb[jj * 4 + 3]) * sc[jj * 4 + 3] + sh[jj * 4 + 3];
            if (do_relu) {
                v0 = fmaxf(v0, 0.f); v1 = fmaxf(v1, 0.f);
                v2 = fmaxf(v2, 0.f); v3 = fmaxf(v3, 0.f);
            }
            o.x = v0; o.y = v1; o.z = v2; o.w = v3;
            *(float4*)(C + (size_t)row * Nc + col) = o;
        }
    }
}

static void run_gemm(const float* A, const float* A2, const float* B,
                     const float* bias, const float* bnp, float* C,
                     int M, int K, int Nc, int do_relu) {
    dim3 grid((Nc + BN - 1) / BN, (M + BM - 1) / BM);
    gemm_bn_kernel<<<grid, 256>>>(A, A2, B, bias, bnp, C, M, K, Nc, do_relu);
}

// ---------------------------------------------------------------------------
// kernel_launch
// ---------------------------------------------------------------------------
extern "C" void kernel_launch(void* const* d_in, const int* in_sizes, int n_in,
                              void* d_out, int out_size) {
    const int*   x         = (const int*)  d_in[0];   // [N,9]
    const int*   edge_idx  = (const int*)  d_in[1];   // [2,E]
    const int*   edge_attr = (const int*)  d_in[2];   // [E,3]
    const int*   batch     = (const int*)  d_in[3];   // [N]
    const float* atom_emb  = (const float*)d_in[4];   // [9,64,D]
    const float* bond_emb  = (const float*)d_in[5];   // [L,3,16,D]
    const float* W1        = (const float*)d_in[6];   // [L,D,2D]
    const float* b1        = (const float*)d_in[7];   // [L,2D]
    const float* bn_in     = (const float*)d_in[8];   // [L,4,2D]
    const float* W2        = (const float*)d_in[9];   // [L,2D,D]
    const float* b2        = (const float*)d_in[10];  // [L,D]
    const float* bn_out    = (const float*)d_in[11];  // [L,4,D]
    const float* vn        = (const float*)d_in[12];  // [1,D]
    const float* vW1       = (const float*)d_in[13];  // [D,2D]
    const float* vb1       = (const float*)d_in[14];
    const float* vbn1      = (const float*)d_in[15];
    const float* vW2       = (const float*)d_in[16];  // [2D,D]
    const float* vb2       = (const float*)d_in[17];
    const float* vbn2      = (const float*)d_in[18];
    float*       out       = (float*)d_out;

    const int N = in_sizes[0] / 9;
    const int E = in_sizes[1] / 2;
    const int G = out_size / DIM;

    float *h, *aggr, *hid, *post, *vfeat, *pooled, *vhid, *cnt;
    cudaGetSymbolAddress((void**)&h,      g_h);
    cudaGetSymbolAddress((void**)&aggr,   g_aggr);
    cudaGetSymbolAddress((void**)&hid,    g_hid);
    cudaGetSymbolAddress((void**)&post,   g_post);
    cudaGetSymbolAddress((void**)&vfeat,  g_vfeat);
    cudaGetSymbolAddress((void**)&pooled, g_pooled);
    cudaGetSymbolAddress((void**)&vhid,   g_vhid);
    cudaGetSymbolAddress((void**)&cnt,    g_cnt);

    const int* src = edge_idx;
    const int* dst = edge_idx + E;

    const int TPB = 256;
    const int nodeC4Blocks = (N * C4 + TPB - 1) / TPB;
    const int edgeC4Blocks = (E * C4 + TPB - 1) / TPB;

    // h = atom encoding; vfeat = vn broadcast; counts
    atom_encode_kernel<<<nodeC4Blocks, TPB>>>(x, atom_emb, h, N);
    vfeat_init_kernel<<<(G * DIM + TPB - 1) / TPB, TPB>>>(vn, vfeat, G);
    cudaMemsetAsync(cnt, 0, (size_t)G * sizeof(float));
    count_kernel<<<(N + TPB - 1) / TPB, TPB>>>(batch, cnt, N);

    for (int l = 0; l < NLAYER; l++) {
        if (l > 0)
            add_vfeat_kernel<<<nodeC4Blocks, TPB>>>(post, vfeat, batch, h, N);

        cudaMemsetAsync(aggr, 0, (size_t)N * DIM * sizeof(float));
        edge_msg_kernel<<<edgeC4Blocks, TPB>>>(
            h, src, dst, edge_attr, bond_emb + (size_t)l * 3 * 16 * DIM, aggr, E);

        // z = h + aggr; hid = relu(bn_in(z@W1 + b1))
        run_gemm(h, aggr, W1 + (size_t)l * DIM * HID, b1 + (size_t)l * HID,
                 bn_in + (size_t)l * 4 * HID, hid, N, DIM, HID, 1);
        // post = bn_out(hid@W2 + b2) (+relu except last layer)
        run_gemm(hid, nullptr, W2 + (size_t)l * HID * DIM, b2 + (size_t)l * DIM,
                 bn_out + (size_t)l * 4 * DIM, post, N, HID, DIM, (l < NLAYER - 1) ? 1 : 0);

        if (l >= 1 && l < NLAYER - 1) {
            // virtual-node update
            cudaMemsetAsync(pooled, 0, (size_t)G * DIM * sizeof(float));
            pool_kernel<<<nodeC4Blocks, TPB>>>(post, batch, pooled, N);
            run_gemm(pooled, vfeat, vW1, vb1, vbn1, vhid, G, DIM, HID, 1);
            run_gemm(vhid, nullptr, vW2, vb2, vbn2, vfeat, G, HID, DIM, 1);
        }
    }

    // readout: mean pool
    cudaMemsetAsync(pooled, 0, (size_t)G * DIM * sizeof(float));
    pool_kernel<<<nodeC4Blocks, TPB>>>(post, batch, pooled, N);
    out_kernel<<<(G * DIM + TPB - 1) / TPB, TPB>>>(pooled, cnt, out, G);
}

// round 5
// speedup vs baseline: 1.5472x; 1.5472x over previous
#include <cuda_runtime.h>
#include <cuda_bf16.h>
#include <cstdint>

// ---------------------------------------------------------------------------
// vGINMolEncoder: 5-layer GINEConv + virtual node, eval-mode BN, mean-pool.
// GEMMs on tensor cores: 3xTF32 error-compensated mma.sync (near-fp32 accuracy).
// ---------------------------------------------------------------------------

#define MAXN 200000
#define MAXE 800000
#define MAXG 8000
#define DIM  300
#define HID  600
#define NLAYER 5
#define EPS_BN 1e-5f
#define C4 75            // DIM / 4

__device__ __align__(256) float g_h     [(size_t)MAXN * DIM];
__device__ __align__(256) float g_aggr  [(size_t)MAXN * DIM];   // pre-filled with h, edge atomics on top
__device__ __align__(256) float g_hid   [(size_t)MAXN * HID];
__device__ __align__(256) float g_post  [(size_t)MAXN * DIM];
__device__ __align__(256) float g_vfeat [(size_t)MAXG * DIM];
__device__ __align__(256) float g_pooled[(size_t)MAXG * DIM];
__device__ __align__(256) float g_vhid  [(size_t)MAXG * HID];
__device__ __align__(256) float g_cnt   [MAXG];

// ---------------------------------------------------------------------------
// Elementwise / scatter kernels
// ---------------------------------------------------------------------------
__global__ void atom_encode_kernel(const int* __restrict__ x,
                                   const float* __restrict__ atom_emb,
                                   float* __restrict__ h,
                                   float* __restrict__ aggr, int N) {
    int idx = blockIdx.x * blockDim.x + threadIdx.x;
    if (idx >= N * C4) return;
    int n = idx / C4;
    int c = (idx - n * C4) * 4;
    float4 s = make_float4(0.f, 0.f, 0.f, 0.f);
#pragma unroll
    for (int f = 0; f < 9; f++) {
        int v = x[n * 9 + f];
        const float4 e = *(const float4*)(atom_emb + ((size_t)(f * 64 + v)) * DIM + c);
        s.x += e.x; s.y += e.y; s.z += e.z; s.w += e.w;
    }
    *(float4*)(h    + (size_t)n * DIM + c) = s;
    *(float4*)(aggr + (size_t)n * DIM + c) = s;
}

__global__ void edge_msg_kernel(const float* __restrict__ h,
                                const int* __restrict__ src,
                                const int* __restrict__ dst,
                                const int* __restrict__ ea,
                                const float* __restrict__ bond_l,   // [3,16,DIM]
                                float* __restrict__ aggr, int E) {
    int idx = blockIdx.x * blockDim.x + threadIdx.x;
    if (idx >= E * C4) return;
    int e  = idx / C4;
    int c  = (idx - e * C4) * 4;
    int s  = src[e];
    int dn = dst[e];
    int a0 = ea[e * 3 + 0], a1 = ea[e * 3 + 1], a2 = ea[e * 3 + 2];
    const float4 b0 = *(const float4*)(bond_l + ((size_t)(0 * 16 + a0)) * DIM + c);
    const float4 b1 = *(const float4*)(bond_l + ((size_t)(1 * 16 + a1)) * DIM + c);
    const float4 b2 = *(const float4*)(bond_l + ((size_t)(2 * 16 + a2)) * DIM + c);
    const float4 hv = *(const float4*)(h + (size_t)s * DIM + c);
    float4 m;
    m.x = fmaxf(hv.x + b0.x + b1.x + b2.x, 0.f);
    m.y = fmaxf(hv.y + b0.y + b1.y + b2.y, 0.f);
    m.z = fmaxf(hv.z + b0.z + b1.z + b2.z, 0.f);
    m.w = fmaxf(hv.w + b0.w + b1.w + b2.w, 0.f);
    float* p = aggr + (size_t)dn * DIM + c;
    atomicAdd(p + 0, m.x);
    atomicAdd(p + 1, m.y);
    atomicAdd(p + 2, m.z);
    atomicAdd(p + 3, m.w);
}

// h = post + vfeat[batch]; also copied into aggr (base for edge scatter)
__global__ void add_vfeat_kernel(const float* __restrict__ post,
                                 const float* __restrict__ vfeat,
                                 const int* __restrict__ batch,
                                 float* __restrict__ h,
                                 float* __restrict__ aggr, int N) {
    int idx = blockIdx.x * blockDim.x + threadIdx.x;
    if (idx >= N * C4) return;
    int n = idx / C4;
    int c = (idx - n * C4) * 4;
    int g = batch[n];
    const float4 p = *(const float4*)(post  + (size_t)n * DIM + c);
    const float4 v = *(const float4*)(vfeat + (size_t)g * DIM + c);
    float4 o = make_float4(p.x + v.x, p.y + v.y, p.z + v.z, p.w + v.w);
    *(float4*)(h    + (size_t)n * DIM + c) = o;
    *(float4*)(aggr + (size_t)n * DIM + c) = o;
}

__global__ void pool_kernel(const float* __restrict__ post,
                            const int* __restrict__ batch,
                            float* __restrict__ pooled, int N) {
    int idx = blockIdx.x * blockDim.x + threadIdx.x;
    if (idx >= N * C4) return;
    int n = idx / C4;
    int c = (idx - n * C4) * 4;
    int g = batch[n];
    const float4 p = *(const float4*)(post + (size_t)n * DIM + c);
    float* q = pooled + (size_t)g * DIM + c;
    atomicAdd(q + 0, p.x);
    atomicAdd(q + 1, p.y);
    atomicAdd(q + 2, p.z);
    atomicAdd(q + 3, p.w);
}

__global__ void count_kernel(const int* __restrict__ batch, float* __restrict__ cnt, int N) {
    int i = blockIdx.x * blockDim.x + threadIdx.x;
    if (i < N) atomicAdd(&cnt[batch[i]], 1.0f);
}

__global__ void vfeat_init_kernel(const float* __restrict__ vn, float* __restrict__ vfeat, int G) {
    int idx = blockIdx.x * blockDim.x + threadIdx.x;
    if (idx >= G * DIM) return;
    vfeat[idx] = vn[idx % DIM];
}

__global__ void copy_kernel(const float* __restrict__ src, float* __restrict__ dst, int n4) {
    int idx = blockIdx.x * blockDim.x + threadIdx.x;
    if (idx >= n4) return;
    *(float4*)(dst + idx * 4) = *(const float4*)(src + idx * 4);
}

__global__ void out_kernel(const float* __restrict__ pooled, const float* __restrict__ cnt,
                           float* __restrict__ out, int G) {
    int idx = blockIdx.x * blockDim.x + threadIdx.x;
    if (idx >= G * DIM) return;
    int g = idx / DIM;
    out[idx] = pooled[idx] / fmaxf(cnt[g], 1.0f);
}

// ---------------------------------------------------------------------------
// 3xTF32 tensor-core GEMM with fused BN(+ReLU) epilogue.
// C = epi(A @ B + bias). A:[M,K] rm, B:[K,Nc] rm, bnp:[4,Nc].
// Each operand split x = hi + lo (hi = tf32-truncated bits); accumulate
// A_hi*B_lo + A_lo*B_hi + A_hi*B_hi -> near-fp32 precision.
// 128x128x16 tile, 256 threads (8 warps, 4x2), warp tile 32x64, m16n8k8.
// ---------------------------------------------------------------------------
#define GBM 128
#define GBN 128
#define GBK 16
#define LDA 20    // GBK + 4 -> conflict-free A fragment loads
#define LDB 136   // GBN + 8 -> conflict-free B fragment loads

__device__ __forceinline__ void cp_async16(uint32_t saddr, const void* gptr, int src_bytes) {
    asm volatile("cp.async.cg.shared.global [%0], [%1], 16, %2;\n"
                 :: "r"(saddr), "l"(gptr), "r"(src_bytes));
}
__device__ __forceinline__ void cp_commit() {
    asm volatile("cp.async.commit_group;\n" ::);
}
template <int N>
__device__ __forceinline__ void cp_wait() {
    asm volatile("cp.async.wait_group %0;\n" :: "n"(N));
}
__device__ __forceinline__ void mma_tf32(float* d, const uint32_t* a, const uint32_t* b) {
    asm volatile(
        "mma.sync.aligned.m16n8k8.row.col.f32.tf32.tf32.f32 "
        "{%0,%1,%2,%3}, {%4,%5,%6,%7}, {%8,%9}, {%0,%1,%2,%3};\n"
        : "+f"(d[0]), "+f"(d[1]), "+f"(d[2]), "+f"(d[3])
        : "r"(a[0]), "r"(a[1]), "r"(a[2]), "r"(a[3]), "r"(b[0]), "r"(b[1]));
}

// split fp32 bits into tf32-high part and fp32 residual (as bits)
__device__ __forceinline__ void tf32_split(uint32_t v, uint32_t& hi, uint32_t& lo) {
    hi = v & 0xFFFFE000u;
    lo = __float_as_uint(__uint_as_float(v) - __uint_as_float(hi));
}

__global__ __launch_bounds__(256) void gemm_tf32_bn(
    const float* __restrict__ A, const float* __restrict__ B,
    const float* __restrict__ bias, const float* __restrict__ bnp,
    float* __restrict__ C, int M, int K, int Nc, int do_relu) {

    __shared__ float As[2][GBM][LDA];
    __shared__ float Bs[2][GBK][LDB];

    const int tid = threadIdx.x;
    const int w = tid >> 5, l = tid & 31;
    const int wm = (w & 3) * 32;
    const int wn = (w >> 2) * 64;
    const int m0 = blockIdx.y * GBM;
    const int n0 = blockIdx.x * GBN;
    const int iters = (K + GBK - 1) / GBK;

    const int qr = l >> 2;   // 0..7
    const int qc = l & 3;    // 0..3

    const int a_row = tid >> 2;
    const int a_kc  = (tid & 3) * 4;
    const int b_row = tid >> 5;
    const int b_nc  = (tid & 31) * 4;

    float acc[2][8][4];
#pragma unroll
    for (int mi = 0; mi < 2; mi++)
#pragma unroll
        for (int ni = 0; ni < 8; ni++)
#pragma unroll
            for (int r = 0; r < 4; r++) acc[mi][ni][r] = 0.f;

    auto issue_load = [&](int it, int buf) {
        const int k0 = it * GBK;
#pragma unroll
        for (int i = 0; i < 2; i++) {
            int row = a_row + i * 64;
            int gm = m0 + row, gk = k0 + a_kc;
            int ok = (gm < M) && (gk + 4 <= K);
            const float* src = A + (size_t)(ok ? gm : 0) * K + (ok ? gk : 0);
            uint32_t dst = (uint32_t)__cvta_generic_to_shared(&As[buf][row][a_kc]);
            cp_async16(dst, src, ok ? 16 : 0);
        }
#pragma unroll
        for (int i = 0; i < 2; i++) {
            int row = b_row + i * 8;
            int gk = k0 + row, gn = n0 + b_nc;
            int ok = (gk < K) && (gn + 4 <= Nc);
            const float* src = B + (size_t)(ok ? gk : 0) * Nc + (ok ? gn : 0);
            uint32_t dst = (uint32_t)__cvta_generic_to_shared(&Bs[buf][row][b_nc]);
            cp_async16(dst, src, ok ? 16 : 0);
        }
        cp_commit();
    };

    issue_load(0, 0);

    for (int it = 0; it < iters; it++) {
        const int buf = it & 1;
        if (it + 1 < iters) {
            issue_load(it + 1, buf ^ 1);
            cp_wait<1>();
        } else {
            cp_wait<0>();
        }
        __syncthreads();

#pragma unroll
        for (int ks = 0; ks < 2; ks++) {
            const int kb = ks * 8;
            uint32_t ah[2][4], al[2][4], bh[8][2], bl[8][2];
#pragma unroll
            for (int mi = 0; mi < 2; mi++) {
                const float* Ap = &As[buf][wm + mi * 16 + qr][kb + qc];
                uint32_t v0 = __float_as_uint(Ap[0]);
                uint32_t v1 = __float_as_uint(Ap[8 * LDA]);
                uint32_t v2 = __float_as_uint(Ap[4]);
                uint32_t v3 = __float_as_uint(Ap[8 * LDA + 4]);
                tf32_split(v0, ah[mi][0], al[mi][0]);
                tf32_split(v1, ah[mi][1], al[mi][1]);
                tf32_split(v2, ah[mi][2], al[mi][2]);
                tf32_split(v3, ah[mi][3], al[mi][3]);
            }
#pragma unroll
            for (int ni = 0; ni < 8; ni++) {
                const float* Bp = &Bs[buf][kb + qc][wn + ni * 8 + qr];
                uint32_t v0 = __float_as_uint(Bp[0]);
                uint32_t v1 = __float_as_uint(Bp[4 * LDB]);
                tf32_split(v0, bh[ni][0], bl[ni][0]);
                tf32_split(v1, bh[ni][1], bl[ni][1]);
            }
#pragma unroll
            for (int mi = 0; mi < 2; mi++)
#pragma unroll
                for (int ni = 0; ni < 8; ni++) {
                    mma_tf32(acc[mi][ni], ah[mi], bl[ni]);
                    mma_tf32(acc[mi][ni], al[mi], bh[ni]);
                    mma_tf32(acc[mi][ni], ah[mi], bh[ni]);
                }
        }
        __syncthreads();
    }

    // -------- epilogue: bias -> BN -> (ReLU) --------
#pragma unroll
    for (int ni = 0; ni < 8; ni++) {
        int col = n0 + wn + ni * 8 + qc * 2;
        if (col >= Nc) continue;   // Nc even, col even -> col+1 also valid
        float bb0 = bias[col], bb1 = bias[col + 1];
        float ga0 = bnp[col],          be0 = bnp[Nc + col];
        float mu0 = bnp[2 * Nc + col], va0 = bnp[3 * Nc + col];
        float ga1 = bnp[col + 1],          be1 = bnp[Nc + col + 1];
        float mu1 = bnp[2 * Nc + col + 1], va1 = bnp[3 * Nc + col + 1];
        float s0 = ga0 * rsqrtf(va0 + EPS_BN), t0 = be0 - mu0 * s0;
        float s1 = ga1 * rsqrtf(va1 + EPS_BN), t1 = be1 - mu1 * s1;
#pragma unroll
        for (int mi = 0; mi < 2; mi++) {
#pragma unroll
            for (int r = 0; r < 2; r++) {
                int row = m0 + wm + mi * 16 + qr + r * 8;
                if (row >= M) continue;
                float v0 = (acc[mi][ni][r * 2 + 0] + bb0) * s0 + t0;
                float v1 = (acc[mi][ni][r * 2 + 1] + bb1) * s1 + t1;
                if (do_relu) { v0 = fmaxf(v0, 0.f); v1 = fmaxf(v1, 0.f); }
                *(float2*)(C + (size_t)row * Nc + col) = make_float2(v0, v1);
            }
        }
    }
}

static void run_gemm(const float* A, const float* B, const float* bias,
                     const float* bnp, float* C, int M, int K, int Nc, int do_relu) {
    dim3 grid((Nc + GBN - 1) / GBN, (M + GBM - 1) / GBM);
    gemm_tf32_bn<<<grid, 256>>>(A, B, bias, bnp, C, M, K, Nc, do_relu);
}

// ---------------------------------------------------------------------------
// kernel_launch
// ---------------------------------------------------------------------------
extern "C" void kernel_launch(void* const* d_in, const int* in_sizes, int n_in,
                              void* d_out, int out_size) {
    const int*   x         = (const int*)  d_in[0];
    const int*   edge_idx  = (const int*)  d_in[1];
    const int*   edge_attr = (const int*)  d_in[2];
    const int*   batch     = (const int*)  d_in[3];
    const float* atom_emb  = (const float*)d_in[4];
    const float* bond_emb  = (const float*)d_in[5];
    const float* W1        = (const float*)d_in[6];
    const float* b1        = (const float*)d_in[7];
    const float* bn_in     = (const float*)d_in[8];
    const float* W2        = (const float*)d_in[9];
    const float* b2        = (const float*)d_in[10];
    const float* bn_out    = (const float*)d_in[11];
    const float* vn        = (const float*)d_in[12];
    const float* vW1       = (const float*)d_in[13];
    const float* vb1       = (const float*)d_in[14];
    const float* vbn1      = (const float*)d_in[15];
    const float* vW2       = (const float*)d_in[16];
    const float* vb2       = (const float*)d_in[17];
    const float* vbn2      = (const float*)d_in[18];
    float*       out       = (float*)d_out;

    const int N = in_sizes[0] / 9;
    const int E = in_sizes[1] / 2;
    const int G = out_size / DIM;

    float *h, *aggr, *hid, *post, *vfeat, *pooled, *vhid, *cnt;
    cudaGetSymbolAddress((void**)&h,      g_h);
    cudaGetSymbolAddress((void**)&aggr,   g_aggr);
    cudaGetSymbolAddress((void**)&hid,    g_hid);
    cudaGetSymbolAddress((void**)&post,   g_post);
    cudaGetSymbolAddress((void**)&vfeat,  g_vfeat);
    cudaGetSymbolAddress((void**)&pooled, g_pooled);
    cudaGetSymbolAddress((void**)&vhid,   g_vhid);
    cudaGetSymbolAddress((void**)&cnt,    g_cnt);

    const int* src = edge_idx;
    const int* dst = edge_idx + E;

    const int TPB = 256;
    const int nodeC4Blocks = (N * C4 + TPB - 1) / TPB;
    const int edgeC4Blocks = (E * C4 + TPB - 1) / TPB;

    atom_encode_kernel<<<nodeC4Blocks, TPB>>>(x, atom_emb, h, aggr, N);
    vfeat_init_kernel<<<(G * DIM + TPB - 1) / TPB, TPB>>>(vn, vfeat, G);
    cudaMemsetAsync(cnt, 0, (size_t)G * sizeof(float));
    count_kernel<<<(N + TPB - 1) / TPB, TPB>>>(batch, cnt, N);

    for (int l = 0; l < NLAYER; l++) {
        if (l > 0)
            add_vfeat_kernel<<<nodeC4Blocks, TPB>>>(post, vfeat, batch, h, aggr, N);

        // aggr already holds h; edge atomics produce z = h + sum(msg)
        edge_msg_kernel<<<edgeC4Blocks, TPB>>>(
            h, src, dst, edge_attr, bond_emb + (size_t)l * 3 * 16 * DIM, aggr, E);

        // hid = relu(bn_in(z @ W1 + b1))
        run_gemm(aggr, W1 + (size_t)l * DIM * HID, b1 + (size_t)l * HID,
                 bn_in + (size_t)l * 4 * HID, hid, N, DIM, HID, 1);
        // post = bn_out(hid @ W2 + b2) (+relu except last layer)
        run_gemm(hid, W2 + (size_t)l * HID * DIM, b2 + (size_t)l * DIM,
                 bn_out + (size_t)l * 4 * DIM, post, N, HID, DIM, (l < NLAYER - 1) ? 1 : 0);

        if (l >= 1 && l < NLAYER - 1) {
            // virtual-node update: pooled starts as vfeat, accumulate node sums
            copy_kernel<<<(G * C4 + TPB - 1) / TPB, TPB>>>(vfeat, pooled, G * C4);
            pool_kernel<<<nodeC4Blocks, TPB>>>(post, batch, pooled, N);
            run_gemm(pooled, vW1, vb1, vbn1, vhid, G, DIM, HID, 1);
            run_gemm(vhid, vW2, vb2, vbn2, vfeat, G, HID, DIM, 1);
        }
    }

    // readout: mean pool
    cudaMemsetAsync(pooled, 0, (size_t)G * DIM * sizeof(float));
    pool_kernel<<<nodeC4Blocks, TPB>>>(post, batch, pooled, N);
    out_kernel<<<(G * DIM + TPB - 1) / TPB, TPB>>>(pooled, cnt, out, G);
}